// round 6
// baseline (speedup 1.0000x reference)
#include <cuda_runtime.h>
#include <cstdint>

#define N_NODES 50000
#define MAX_E   800000
#define D 96
#define D4 (D/4)
#define TILE_ROWS 24
#define TX 24
#define TY 4
#define RPT 6
#define NBLK ((N_NODES + 255) / 256)        // 196 scan blocks
#define GEMM_BLOCKS ((N_NODES + TILE_ROWS - 1) / TILE_ROWS)  // 2084
#define FILL_CHUNK (96 * 32)                 // edges per fill block

// ---- device scratch (zero-initialized at module load; k_agg restores zeros) ----
__device__ int   g_deg_out_i[N_NODES];
__device__ int   g_deg_in_i[N_NODES];
__device__ int   g_row_ptr[N_NODES + 1];
__device__ int   g_fill[N_NODES];
__device__ int   g_aggr[NBLK];
__device__ int   g_flag[NBLK];               // must be 0 at kernel entry
__device__ int   g_csr_src[MAX_E];
__device__ float g_h[(size_t)N_NODES * D];   // (x@W) * inv_sqrt(deg_out)

// ---- kernel: degree counts (counters are pre-zeroed by invariant) ----
__global__ void k_deg(const int* __restrict__ src,
                      const int* __restrict__ dst, int E) {
    int e = blockIdx.x * blockDim.x + threadIdx.x;
    if (e < E) {
        atomicAdd(&g_deg_out_i[src[e]], 1);
        atomicAdd(&g_deg_in_i[dst[e]], 1);
    }
}

// ---- kernel: single-launch exclusive scan (decoupled lookback) ----
__global__ __launch_bounds__(256)
void k_scan(int E) {
    __shared__ int sh[256];
    int i = blockIdx.x * 256 + threadIdx.x;
    int v = (i < N_NODES) ? g_deg_in_i[i] : 0;
    sh[threadIdx.x] = v;
    __syncthreads();
    #pragma unroll
    for (int off = 1; off < 256; off <<= 1) {
        int t = (threadIdx.x >= off) ? sh[threadIdx.x - off] : 0;
        __syncthreads();
        sh[threadIdx.x] += t;
        __syncthreads();
    }
    int incl = sh[threadIdx.x];
    int block_total = sh[255];
    __syncthreads();

    // publish this block's aggregate
    if (threadIdx.x == 0) {
        g_aggr[blockIdx.x] = block_total;
        __threadfence();
        *((volatile int*)&g_flag[blockIdx.x]) = 1;
    }

    // lookback: thread t waits for predecessor block t (all blocks resident)
    int contrib = 0;
    if (threadIdx.x < blockIdx.x) {
        while (*((volatile int*)&g_flag[threadIdx.x]) == 0) {}
        __threadfence();
        contrib = *((volatile int*)&g_aggr[threadIdx.x]);
    }
    sh[threadIdx.x] = contrib;
    __syncthreads();
    #pragma unroll
    for (int off = 128; off > 0; off >>= 1) {
        if (threadIdx.x < off) sh[threadIdx.x] += sh[threadIdx.x + off];
        __syncthreads();
    }
    int base = sh[0];

    if (i < N_NODES) {
        int p = base + incl - v;   // exclusive prefix
        g_row_ptr[i] = p;
        g_fill[i] = p;
    }
    if (i == 0) g_row_ptr[N_NODES] = E;
}

// ---- fused kernel: fill blocks first (overlap), then gemm blocks ----
__global__ __launch_bounds__(TX * TY)
void k_fillgemm(const float* __restrict__ x, const float* __restrict__ Wg,
                const int* __restrict__ src, const int* __restrict__ dst,
                int E, int fill_blocks) {
    __shared__ float Ws[D * D];          // 36864 B
    __shared__ float xs[TILE_ROWS * D];  //  9216 B  (total 46080 B)

    const int tid = threadIdx.y * TX + threadIdx.x;
    const int nth = TX * TY;             // 96

    if ((int)blockIdx.x < fill_blocks) {
        // ---- fill path: bucket edges by dst ----
        int base = blockIdx.x * FILL_CHUNK;
        #pragma unroll 4
        for (int k = 0; k < 32; k++) {
            int e = base + k * nth + tid;
            if (e < E) {
                int d = dst[e];
                int pos = atomicAdd(&g_fill[d], 1);
                g_csr_src[pos] = src[e];
            }
        }
        return;
    }

    // ---- gemm path ----
    const int gb = blockIdx.x - fill_blocks;

    for (int i = tid; i < D * D / 4; i += nth)
        ((float4*)Ws)[i] = ((const float4*)Wg)[i];

    const int rbase = gb * TILE_ROWS;

    for (int i = tid; i < TILE_ROWS * D4; i += nth) {
        int r = i / D4, c = i % D4;
        int g = rbase + r;
        float4 v = make_float4(0.f, 0.f, 0.f, 0.f);
        if (g < N_NODES) v = ((const float4*)(x + (size_t)g * D))[c];
        ((float4*)xs)[r * D4 + c] = v;
    }
    __syncthreads();

    float4 acc[RPT];
    #pragma unroll
    for (int r = 0; r < RPT; r++) acc[r] = make_float4(0.f, 0.f, 0.f, 0.f);

    const int tx4 = threadIdx.x * 4;
    const int ry  = threadIdx.y * RPT;

    #pragma unroll
    for (int k = 0; k < D; k += 4) {
        float4 w0 = *(const float4*)&Ws[(k + 0) * D + tx4];
        float4 w1 = *(const float4*)&Ws[(k + 1) * D + tx4];
        float4 w2 = *(const float4*)&Ws[(k + 2) * D + tx4];
        float4 w3 = *(const float4*)&Ws[(k + 3) * D + tx4];
        #pragma unroll
        for (int r = 0; r < RPT; r++) {
            float4 xv = *(const float4*)&xs[(ry + r) * D + k];
            acc[r].x += xv.x * w0.x + xv.y * w1.x + xv.z * w2.x + xv.w * w3.x;
            acc[r].y += xv.x * w0.y + xv.y * w1.y + xv.z * w2.y + xv.w * w3.y;
            acc[r].z += xv.x * w0.z + xv.y * w1.z + xv.z * w2.z + xv.w * w3.z;
            acc[r].w += xv.x * w0.w + xv.y * w1.w + xv.z * w2.w + xv.w * w3.w;
        }
    }

    #pragma unroll
    for (int r = 0; r < RPT; r++) {
        int row = rbase + ry + r;
        if (row < N_NODES) {
            float dg  = (float)g_deg_out_i[row];
            float inv = dg > 0.f ? rsqrtf(dg) : 0.f;
            float4 o = make_float4(acc[r].x * inv, acc[r].y * inv,
                                   acc[r].z * inv, acc[r].w * inv);
            *(float4*)&g_h[(size_t)row * D + tx4] = o;
        }
    }
}

// ---- kernel: aggregate per dst node (one warp per node, no atomics) ----
// Epilogue restores the zero-invariant on counters/flags for the next replay.
__global__ __launch_bounds__(256)
void k_agg(const float* __restrict__ b, float* __restrict__ out) {
    int warp = (blockIdx.x * blockDim.x + threadIdx.x) >> 5;
    int lane = threadIdx.x & 31;
    if (warp >= N_NODES) return;

    int beg = g_row_ptr[warp];
    int end = g_row_ptr[warp + 1];

    float a0 = 0.f, a1 = 0.f, a2 = 0.f;

    int j = beg;
    // 4-edge unrolled: 12 independent h-loads in flight
    for (; j + 3 < end; j += 4) {
        int s0 = __ldg(&g_csr_src[j]);
        int s1 = __ldg(&g_csr_src[j + 1]);
        int s2 = __ldg(&g_csr_src[j + 2]);
        int s3 = __ldg(&g_csr_src[j + 3]);
        const float* h0 = g_h + (size_t)s0 * D;
        const float* h1 = g_h + (size_t)s1 * D;
        const float* h2 = g_h + (size_t)s2 * D;
        const float* h3 = g_h + (size_t)s3 * D;
        float v00 = __ldg(h0 + lane), v01 = __ldg(h0 + lane + 32), v02 = __ldg(h0 + lane + 64);
        float v10 = __ldg(h1 + lane), v11 = __ldg(h1 + lane + 32), v12 = __ldg(h1 + lane + 64);
        float v20 = __ldg(h2 + lane), v21 = __ldg(h2 + lane + 32), v22 = __ldg(h2 + lane + 64);
        float v30 = __ldg(h3 + lane), v31 = __ldg(h3 + lane + 32), v32 = __ldg(h3 + lane + 64);
        a0 += (v00 + v10) + (v20 + v30);
        a1 += (v01 + v11) + (v21 + v31);
        a2 += (v02 + v12) + (v22 + v32);
    }
    for (; j < end; j++) {
        int s = __ldg(&g_csr_src[j]);
        const float* hp = g_h + (size_t)s * D;
        a0 += __ldg(hp + lane);
        a1 += __ldg(hp + lane + 32);
        a2 += __ldg(hp + lane + 64);
    }

    float dg  = (float)g_deg_in_i[warp];
    float inv = dg > 0.f ? rsqrtf(dg) : 0.f;

    float* op = out + (size_t)warp * D;
    op[lane]      = a0 * inv + b[lane];
    op[lane + 32] = a1 * inv + b[lane + 32];
    op[lane + 64] = a2 * inv + b[lane + 64];

    // restore zero-invariant for the next graph replay
    if (lane == 0) {
        g_deg_in_i[warp]  = 0;
        g_deg_out_i[warp] = 0;
    }
    if (lane == 1 && warp < NBLK) g_flag[warp] = 0;
}

extern "C" void kernel_launch(void* const* d_in, const int* in_sizes, int n_in,
                              void* d_out, int out_size) {
    const float* x   = (const float*)d_in[0];
    const float* W   = (const float*)d_in[1];
    const float* b   = (const float*)d_in[2];
    const int*   src = (const int*)d_in[3];
    const int*   dst = (const int*)d_in[4];
    float* out = (float*)d_out;
    const int E = in_sizes[3];

    k_deg<<<(E + 255) / 256, 256>>>(src, dst, E);
    k_scan<<<NBLK, 256>>>(E);

    int fill_blocks = (E + FILL_CHUNK - 1) / FILL_CHUNK;   // 261 for E=800000
    k_fillgemm<<<fill_blocks + GEMM_BLOCKS, dim3(TX, TY)>>>(x, W, src, dst, E, fill_blocks);

    long long agg_threads = (long long)N_NODES * 32;
    k_agg<<<(int)((agg_threads + 255) / 256), 256>>>(b, out);
}

// round 7
// speedup vs baseline: 1.0053x; 1.0053x over previous
#include <cuda_runtime.h>
#include <cstdint>

#define N_NODES 50000
#define MAX_E   800000
#define D 96
#define D4 (D/4)
#define TILE_ROWS 24
#define TX 24
#define TY 8
#define RPT 3
#define NBLK ((N_NODES + 255) / 256)        // 196 scan blocks

// ---- device scratch (zero-initialized at module load; k_agg restores zeros) ----
__device__ int   g_deg_out_i[N_NODES];
__device__ int   g_deg_in_i[N_NODES];
__device__ int   g_row_ptr[N_NODES + 1];
__device__ int   g_fill[N_NODES];
__device__ int   g_aggr[NBLK];
__device__ int   g_flag[NBLK];               // must be 0 at kernel entry
__device__ int   g_csr_src[MAX_E];
__device__ float g_h[(size_t)N_NODES * D];   // (x@W) * inv_sqrt(deg_out)

// ---- kernel: degree counts (counters pre-zeroed by invariant) ----
__global__ void k_deg(const int* __restrict__ src,
                      const int* __restrict__ dst, int E) {
    int e = blockIdx.x * blockDim.x + threadIdx.x;
    if (e < E) {
        atomicAdd(&g_deg_out_i[src[e]], 1);
        atomicAdd(&g_deg_in_i[dst[e]], 1);
    }
}

// ---- kernel: single-launch exclusive scan (decoupled lookback) ----
__global__ __launch_bounds__(256)
void k_scan(int E) {
    __shared__ int sh[256];
    int i = blockIdx.x * 256 + threadIdx.x;
    int v = (i < N_NODES) ? g_deg_in_i[i] : 0;
    sh[threadIdx.x] = v;
    __syncthreads();
    #pragma unroll
    for (int off = 1; off < 256; off <<= 1) {
        int t = (threadIdx.x >= off) ? sh[threadIdx.x - off] : 0;
        __syncthreads();
        sh[threadIdx.x] += t;
        __syncthreads();
    }
    int incl = sh[threadIdx.x];
    int block_total = sh[255];
    __syncthreads();

    if (threadIdx.x == 0) {
        g_aggr[blockIdx.x] = block_total;
        __threadfence();
        *((volatile int*)&g_flag[blockIdx.x]) = 1;
    }

    int contrib = 0;
    if (threadIdx.x < blockIdx.x) {
        while (*((volatile int*)&g_flag[threadIdx.x]) == 0) {}
        __threadfence();
        contrib = *((volatile int*)&g_aggr[threadIdx.x]);
    }
    sh[threadIdx.x] = contrib;
    __syncthreads();
    #pragma unroll
    for (int off = 128; off > 0; off >>= 1) {
        if (threadIdx.x < off) sh[threadIdx.x] += sh[threadIdx.x + off];
        __syncthreads();
    }
    int base = sh[0];

    if (i < N_NODES) {
        int p = base + incl - v;   // exclusive prefix
        g_row_ptr[i] = p;
        g_fill[i] = p;
    }
    if (i == 0) g_row_ptr[N_NODES] = E;
}

// ---- kernel: bucket edges by dst ----
__global__ void k_fill(const int* __restrict__ src,
                       const int* __restrict__ dst, int E) {
    int e = blockIdx.x * blockDim.x + threadIdx.x;
    if (e < E) {
        int d = dst[e];
        int pos = atomicAdd(&g_fill[d], 1);
        g_csr_src[pos] = src[e];
    }
}

// ---- kernel: h_scaled = (x @ W) * inv_sqrt(deg_out)  (R4-proven config) ----
__global__ __launch_bounds__(TX * TY)
void k_gemm(const float* __restrict__ x, const float* __restrict__ Wg) {
    __shared__ float Ws[D * D];          // 36864 B
    __shared__ float xs[TILE_ROWS * D];  //  9216 B

    const int tid = threadIdx.y * TX + threadIdx.x;
    const int nth = TX * TY;

    for (int i = tid; i < D * D / 4; i += nth)
        ((float4*)Ws)[i] = ((const float4*)Wg)[i];

    const int rbase = blockIdx.x * TILE_ROWS;

    for (int i = tid; i < TILE_ROWS * D4; i += nth) {
        int r = i / D4, c = i % D4;
        int g = rbase + r;
        float4 v = make_float4(0.f, 0.f, 0.f, 0.f);
        if (g < N_NODES) v = ((const float4*)(x + (size_t)g * D))[c];
        ((float4*)xs)[r * D4 + c] = v;
    }
    __syncthreads();

    float4 acc[RPT];
    #pragma unroll
    for (int r = 0; r < RPT; r++) acc[r] = make_float4(0.f, 0.f, 0.f, 0.f);

    const int tx4 = threadIdx.x * 4;
    const int ry  = threadIdx.y * RPT;

    #pragma unroll
    for (int k = 0; k < D; k += 4) {
        float4 w0 = *(const float4*)&Ws[(k + 0) * D + tx4];
        float4 w1 = *(const float4*)&Ws[(k + 1) * D + tx4];
        float4 w2 = *(const float4*)&Ws[(k + 2) * D + tx4];
        float4 w3 = *(const float4*)&Ws[(k + 3) * D + tx4];
        #pragma unroll
        for (int r = 0; r < RPT; r++) {
            float4 xv = *(const float4*)&xs[(ry + r) * D + k];
            acc[r].x += xv.x * w0.x + xv.y * w1.x + xv.z * w2.x + xv.w * w3.x;
            acc[r].y += xv.x * w0.y + xv.y * w1.y + xv.z * w2.y + xv.w * w3.y;
            acc[r].z += xv.x * w0.z + xv.y * w1.z + xv.z * w2.z + xv.w * w3.z;
            acc[r].w += xv.x * w0.w + xv.y * w1.w + xv.z * w2.w + xv.w * w3.w;
        }
    }

    #pragma unroll
    for (int r = 0; r < RPT; r++) {
        int row = rbase + ry + r;
        if (row < N_NODES) {
            float dg  = (float)g_deg_out_i[row];
            float inv = dg > 0.f ? rsqrtf(dg) : 0.f;
            float4 o = make_float4(acc[r].x * inv, acc[r].y * inv,
                                   acc[r].z * inv, acc[r].w * inv);
            *(float4*)&g_h[(size_t)row * D + tx4] = o;
        }
    }
}

// ---- kernel: aggregate per dst node (one warp/node, float4 lanes, no atomics) ----
// lanes 0-23 each own one float4 column chunk: 1 LDG.128 per edge per warp.
__global__ __launch_bounds__(256)
void k_agg(const float* __restrict__ b, float* __restrict__ out) {
    int warp = (blockIdx.x * blockDim.x + threadIdx.x) >> 5;
    int lane = threadIdx.x & 31;
    if (warp >= N_NODES) return;

    int beg = g_row_ptr[warp];
    int end = g_row_ptr[warp + 1];

    float4 a = make_float4(0.f, 0.f, 0.f, 0.f);

    if (lane < D4) {
        const float4* hbase = (const float4*)g_h;
        int j = beg;
        // 4-edge unroll: 4 independent LDG.128 in flight per lane
        for (; j + 3 < end; j += 4) {
            int s0 = __ldg(&g_csr_src[j]);
            int s1 = __ldg(&g_csr_src[j + 1]);
            int s2 = __ldg(&g_csr_src[j + 2]);
            int s3 = __ldg(&g_csr_src[j + 3]);
            float4 v0 = __ldg(hbase + (size_t)s0 * D4 + lane);
            float4 v1 = __ldg(hbase + (size_t)s1 * D4 + lane);
            float4 v2 = __ldg(hbase + (size_t)s2 * D4 + lane);
            float4 v3 = __ldg(hbase + (size_t)s3 * D4 + lane);
            a.x += (v0.x + v1.x) + (v2.x + v3.x);
            a.y += (v0.y + v1.y) + (v2.y + v3.y);
            a.z += (v0.z + v1.z) + (v2.z + v3.z);
            a.w += (v0.w + v1.w) + (v2.w + v3.w);
        }
        for (; j < end; j++) {
            int s = __ldg(&g_csr_src[j]);
            float4 v = __ldg(hbase + (size_t)s * D4 + lane);
            a.x += v.x; a.y += v.y; a.z += v.z; a.w += v.w;
        }

        float dg  = (float)g_deg_in_i[warp];
        float inv = dg > 0.f ? rsqrtf(dg) : 0.f;
        float4 bb = ((const float4*)b)[lane];
        float4 o  = make_float4(a.x * inv + bb.x, a.y * inv + bb.y,
                                a.z * inv + bb.z, a.w * inv + bb.w);
        ((float4*)(out + (size_t)warp * D))[lane] = o;
    }

    // restore zero-invariant for the next graph replay
    if (lane == 30) {
        g_deg_in_i[warp]  = 0;
        g_deg_out_i[warp] = 0;
    }
    if (lane == 31 && warp < NBLK) g_flag[warp] = 0;
}

extern "C" void kernel_launch(void* const* d_in, const int* in_sizes, int n_in,
                              void* d_out, int out_size) {
    const float* x   = (const float*)d_in[0];
    const float* W   = (const float*)d_in[1];
    const float* b   = (const float*)d_in[2];
    const int*   src = (const int*)d_in[3];
    const int*   dst = (const int*)d_in[4];
    float* out = (float*)d_out;
    const int E = in_sizes[3];

    k_deg<<<(E + 255) / 256, 256>>>(src, dst, E);
    k_scan<<<NBLK, 256>>>(E);
    k_fill<<<(E + 255) / 256, 256>>>(src, dst, E);
    k_gemm<<<(N_NODES + TILE_ROWS - 1) / TILE_ROWS, dim3(TX, TY)>>>(x, W);

    long long agg_threads = (long long)N_NODES * 32;
    k_agg<<<(int)((agg_threads + 255) / 256), 256>>>(b, out);
}

// round 8
// speedup vs baseline: 1.1200x; 1.1141x over previous
#include <cuda_runtime.h>
#include <cstdint>

#define N_NODES 50000
#define MAX_E   800000
#define D 96
#define D4 (D/4)
#define TILE_ROWS 48
#define TX 24
#define TY 8
#define RPT 6
#define KH 48                                // k-phase half
#define NBLK ((N_NODES + 255) / 256)         // 196 scan blocks

// ---- device scratch (zero-init at load; k_agg restores counter zeros) ----
__device__ int   g_deg_out_i[N_NODES];
__device__ int   g_deg_in_i[N_NODES];
__device__ int   g_row_ptr[N_NODES + 1];
__device__ int   g_fill[N_NODES];
__device__ int   g_bsum[256];
__device__ int   g_csr_src[MAX_E];
__device__ float g_h[(size_t)N_NODES * D];   // (x@W) * inv_sqrt(deg_out)

// ---- kernel: degree counts (counters pre-zeroed by invariant) ----
__global__ void k_deg(const int* __restrict__ src,
                      const int* __restrict__ dst, int E) {
    int e = blockIdx.x * blockDim.x + threadIdx.x;
    if (e < E) {
        atomicAdd(&g_deg_out_i[src[e]], 1);
        atomicAdd(&g_deg_in_i[dst[e]], 1);
    }
}

// ---- scan step 1: per-block exclusive scan of deg_in ----
__global__ void k_scan1() {
    __shared__ int sh[256];
    int i = blockIdx.x * 256 + threadIdx.x;
    int v = (i < N_NODES) ? g_deg_in_i[i] : 0;
    sh[threadIdx.x] = v;
    __syncthreads();
    #pragma unroll
    for (int off = 1; off < 256; off <<= 1) {
        int t = (threadIdx.x >= off) ? sh[threadIdx.x - off] : 0;
        __syncthreads();
        sh[threadIdx.x] += t;
        __syncthreads();
    }
    if (i < N_NODES) g_row_ptr[i] = sh[threadIdx.x] - v;
    if (threadIdx.x == 255) g_bsum[blockIdx.x] = sh[255];
}

// ---- scan step 2: exclusive scan of block sums (1 block) ----
__global__ void k_scan2() {
    __shared__ int sh[256];
    int v = (threadIdx.x < NBLK) ? g_bsum[threadIdx.x] : 0;
    sh[threadIdx.x] = v;
    __syncthreads();
    #pragma unroll
    for (int off = 1; off < 256; off <<= 1) {
        int t = (threadIdx.x >= off) ? sh[threadIdx.x - off] : 0;
        __syncthreads();
        sh[threadIdx.x] += t;
        __syncthreads();
    }
    if (threadIdx.x < NBLK) g_bsum[threadIdx.x] = sh[threadIdx.x] - v;
}

// ---- scan step 3: add block offsets, init fill cursors ----
__global__ void k_scan3(int E) {
    int i = blockIdx.x * 256 + threadIdx.x;
    if (i < N_NODES) {
        int p = g_row_ptr[i] + g_bsum[blockIdx.x];
        g_row_ptr[i] = p;
        g_fill[i] = p;
    }
    if (i == 0) g_row_ptr[N_NODES] = E;
}

// ---- kernel: bucket edges by dst ----
__global__ void k_fill(const int* __restrict__ src,
                       const int* __restrict__ dst, int E) {
    int e = blockIdx.x * blockDim.x + threadIdx.x;
    if (e < E) {
        int d = dst[e];
        int pos = atomicAdd(&g_fill[d], 1);
        g_csr_src[pos] = src[e];
    }
}

// ---- kernel: h = (x@W) * inv_sqrt(deg_out), 48-row tiles, 2 k-phases ----
__global__ __launch_bounds__(TX * TY)
void k_gemm(const float* __restrict__ x, const float* __restrict__ Wg) {
    __shared__ float Ws[KH * D];          // 18432 B (one k-half of W)
    __shared__ float xs[TILE_ROWS * D];   // 18432 B  (total 36864 B)

    const int tid = threadIdx.y * TX + threadIdx.x;
    const int nth = TX * TY;              // 192
    const int rbase = blockIdx.x * TILE_ROWS;

    // stage x tile (48 rows, zero-pad past N)
    for (int i = tid; i < TILE_ROWS * D4; i += nth) {
        int r = i / D4, c = i % D4;
        int g = rbase + r;
        float4 v = make_float4(0.f, 0.f, 0.f, 0.f);
        if (g < N_NODES) v = ((const float4*)(x + (size_t)g * D))[c];
        ((float4*)xs)[r * D4 + c] = v;
    }

    float4 acc[RPT];
    #pragma unroll
    for (int r = 0; r < RPT; r++) acc[r] = make_float4(0.f, 0.f, 0.f, 0.f);

    const int tx4 = threadIdx.x * 4;
    const int ry  = threadIdx.y * RPT;

    #pragma unroll
    for (int p = 0; p < 2; p++) {
        __syncthreads();   // protect Ws reuse (and x staging on first pass)
        // stage W rows [p*KH, p*KH+KH)
        for (int i = tid; i < KH * D4; i += nth)
            ((float4*)Ws)[i] = ((const float4*)Wg)[p * KH * D4 + i];
        __syncthreads();

        #pragma unroll
        for (int kk = 0; kk < KH; kk += 4) {
            float4 w0 = *(const float4*)&Ws[(kk + 0) * D + tx4];
            float4 w1 = *(const float4*)&Ws[(kk + 1) * D + tx4];
            float4 w2 = *(const float4*)&Ws[(kk + 2) * D + tx4];
            float4 w3 = *(const float4*)&Ws[(kk + 3) * D + tx4];
            #pragma unroll
            for (int r = 0; r < RPT; r++) {
                float4 xv = *(const float4*)&xs[(ry + r) * D + p * KH + kk];
                acc[r].x += xv.x * w0.x + xv.y * w1.x + xv.z * w2.x + xv.w * w3.x;
                acc[r].y += xv.x * w0.y + xv.y * w1.y + xv.z * w2.y + xv.w * w3.y;
                acc[r].z += xv.x * w0.z + xv.y * w1.z + xv.z * w2.z + xv.w * w3.z;
                acc[r].w += xv.x * w0.w + xv.y * w1.w + xv.z * w2.w + xv.w * w3.w;
            }
        }
    }

    #pragma unroll
    for (int r = 0; r < RPT; r++) {
        int row = rbase + ry + r;
        if (row < N_NODES) {
            float dg  = (float)g_deg_out_i[row];
            float inv = dg > 0.f ? rsqrtf(dg) : 0.f;
            float4 o = make_float4(acc[r].x * inv, acc[r].y * inv,
                                   acc[r].z * inv, acc[r].w * inv);
            *(float4*)&g_h[(size_t)row * D + tx4] = o;
        }
    }
}

// ---- kernel: aggregate per dst node (one warp/node, float4 lanes) ----
__global__ __launch_bounds__(256)
void k_agg(const float* __restrict__ b, float* __restrict__ out) {
    int warp = (blockIdx.x * blockDim.x + threadIdx.x) >> 5;
    int lane = threadIdx.x & 31;
    if (warp >= N_NODES) return;

    int beg = g_row_ptr[warp];
    int end = g_row_ptr[warp + 1];

    if (lane < D4) {
        float4 a = make_float4(0.f, 0.f, 0.f, 0.f);
        const float4* hbase = (const float4*)g_h;
        int j = beg;
        for (; j + 3 < end; j += 4) {
            int s0 = __ldg(&g_csr_src[j]);
            int s1 = __ldg(&g_csr_src[j + 1]);
            int s2 = __ldg(&g_csr_src[j + 2]);
            int s3 = __ldg(&g_csr_src[j + 3]);
            float4 v0 = __ldg(hbase + (size_t)s0 * D4 + lane);
            float4 v1 = __ldg(hbase + (size_t)s1 * D4 + lane);
            float4 v2 = __ldg(hbase + (size_t)s2 * D4 + lane);
            float4 v3 = __ldg(hbase + (size_t)s3 * D4 + lane);
            a.x += (v0.x + v1.x) + (v2.x + v3.x);
            a.y += (v0.y + v1.y) + (v2.y + v3.y);
            a.z += (v0.z + v1.z) + (v2.z + v3.z);
            a.w += (v0.w + v1.w) + (v2.w + v3.w);
        }
        for (; j < end; j++) {
            int s = __ldg(&g_csr_src[j]);
            float4 v = __ldg(hbase + (size_t)s * D4 + lane);
            a.x += v.x; a.y += v.y; a.z += v.z; a.w += v.w;
        }

        float dg  = (float)g_deg_in_i[warp];
        float inv = dg > 0.f ? rsqrtf(dg) : 0.f;
        float4 bb = ((const float4*)b)[lane];
        float4 o  = make_float4(a.x * inv + bb.x, a.y * inv + bb.y,
                                a.z * inv + bb.z, a.w * inv + bb.w);
        ((float4*)(out + (size_t)warp * D))[lane] = o;
    }

    // restore zero-invariant for the next graph replay
    if (lane == 30) {
        g_deg_in_i[warp]  = 0;
        g_deg_out_i[warp] = 0;
    }
}

extern "C" void kernel_launch(void* const* d_in, const int* in_sizes, int n_in,
                              void* d_out, int out_size) {
    const float* x   = (const float*)d_in[0];
    const float* W   = (const float*)d_in[1];
    const float* b   = (const float*)d_in[2];
    const int*   src = (const int*)d_in[3];
    const int*   dst = (const int*)d_in[4];
    float* out = (float*)d_out;
    const int E = in_sizes[3];

    k_deg<<<(E + 255) / 256, 256>>>(src, dst, E);
    k_scan1<<<NBLK, 256>>>();
    k_scan2<<<1, 256>>>();
    k_scan3<<<NBLK, 256>>>(E);
    k_fill<<<(E + 255) / 256, 256>>>(src, dst, E);
    k_gemm<<<(N_NODES + TILE_ROWS - 1) / TILE_ROWS, dim3(TX, TY)>>>(x, W);

    long long agg_threads = (long long)N_NODES * 32;
    k_agg<<<(int)((agg_threads + 255) / 256), 256>>>(b, out);
}